// round 1
// baseline (speedup 1.0000x reference)
#include <cuda_runtime.h>

// LSTM: T=512 steps, B=4096, I=10, H=20. PyTorch gate order i,f,g,o.
// One thread per (batch, hidden_j). Weights register-resident as f32x2 pairs.
// Packed fma.rn.f32x2 (sm_103a) for 2x fp32 FMA throughput.

#define T_STEPS 512
#define BATCH   4096
#define ISZ     10
#define HSZ     20
#define NB      16                 // batch rows per block
#define NTHREADS (NB * HSZ)        // 320

typedef unsigned long long u64;

__device__ __forceinline__ u64 pack2(float x, float y) {
    u64 r;
    asm("mov.b64 %0, {%1,%2};" : "=l"(r) : "f"(x), "f"(y));
    return r;
}
__device__ __forceinline__ void unpack2(u64 v, float& x, float& y) {
    asm("mov.b64 {%0,%1}, %2;" : "=f"(x), "=f"(y) : "l"(v));
}
__device__ __forceinline__ u64 ffma2(u64 a, u64 b, u64 c) {
    u64 r;
    asm("fma.rn.f32x2 %0, %1, %2, %3;" : "=l"(r) : "l"(a), "l"(b), "l"(c));
    return r;
}

__device__ __forceinline__ float sigmoid_f(float x) {
    float e = __expf(-x);                 // MUFU.EX2
    return __fdividef(1.0f, 1.0f + e);    // MUFU.RCP + mul
}
__device__ __forceinline__ float tanh_f(float x) {
    float e = __expf(-2.0f * x);
    return __fdividef(1.0f - e, 1.0f + e);
}

__global__ void __launch_bounds__(NTHREADS, 1) lstm_persist_kernel(
    const float* __restrict__ x,      // [T, B, I]
    const float* __restrict__ h0,     // [B, H]
    const float* __restrict__ c0,     // [B, H]
    const float* __restrict__ Wih,    // [4H, I]
    const float* __restrict__ Whh,    // [4H, H]
    const float* __restrict__ bih,    // [4H]
    const float* __restrict__ bhh,    // [4H]
    float* __restrict__ out,
    long long out_size)
{
    const int tid = threadIdx.x;
    const int bl  = tid / HSZ;            // local batch row 0..NB-1
    const int j   = tid % HSZ;            // hidden unit 0..H-1
    const int b   = blockIdx.x * NB + bl; // global batch row

    // ---- Load weights into registers as packed f32x2 pairs ----
    u64 wih2[4][ISZ / 2];   // 4 gates x 5 pairs
    u64 whh2[4][HSZ / 2];   // 4 gates x 10 pairs
    u64 bias2[4];
#pragma unroll
    for (int g = 0; g < 4; g++) {
        const float* wr = Wih + (g * HSZ + j) * ISZ;   // 40B-aligned rows -> 8B ok
#pragma unroll
        for (int k = 0; k < ISZ / 2; k++)
            wih2[g][k] = *reinterpret_cast<const u64*>(wr + 2 * k);
        const float* wr2 = Whh + (g * HSZ + j) * HSZ;  // 80B-aligned rows
#pragma unroll
        for (int k = 0; k < HSZ / 2; k++)
            whh2[g][k] = *reinterpret_cast<const u64*>(wr2 + 2 * k);
        bias2[g] = pack2(bih[g * HSZ + j] + bhh[g * HSZ + j], 0.0f);
    }

    // ---- Shared h state, double-buffered (one barrier per step) ----
    __shared__ float hs[2][NB][HSZ];   // 2.5 KB

    float c  = c0[(size_t)b * HSZ + j];
    float hn = h0[(size_t)b * HSZ + j];
    hs[0][bl][j] = hn;
    __syncthreads();

    const float* xb = x + (size_t)b * ISZ;
    const size_t out_stride_t = (size_t)BATCH * HSZ;

    for (int t = 0; t < T_STEPS; t++) {
        const int cur = t & 1;

        u64 acc0 = bias2[0], acc1 = bias2[1], acc2 = bias2[2], acc3 = bias2[3];

        // input projection: x[t,b,0:10] read directly from gmem (L1 broadcast
        // across the 20 j-threads sharing this batch row)
        const float* xp = xb + (size_t)t * BATCH * ISZ;
#pragma unroll
        for (int k = 0; k < ISZ / 2; k++) {
            u64 x2 = *reinterpret_cast<const u64*>(xp + 2 * k);
            acc0 = ffma2(wih2[0][k], x2, acc0);
            acc1 = ffma2(wih2[1][k], x2, acc1);
            acc2 = ffma2(wih2[2][k], x2, acc2);
            acc3 = ffma2(wih2[3][k], x2, acc3);
        }

        // recurrent projection from shared h
        const float* hrow = &hs[cur][bl][0];
#pragma unroll
        for (int k = 0; k < HSZ / 2; k++) {
            u64 h2 = *reinterpret_cast<const u64*>(hrow + 2 * k);  // LDS.64
            acc0 = ffma2(whh2[0][k], h2, acc0);
            acc1 = ffma2(whh2[1][k], h2, acc1);
            acc2 = ffma2(whh2[2][k], h2, acc2);
            acc3 = ffma2(whh2[3][k], h2, acc3);
        }

        float lo, hi, gi, gf, gg, go;
        unpack2(acc0, lo, hi); gi = lo + hi;
        unpack2(acc1, lo, hi); gf = lo + hi;
        unpack2(acc2, lo, hi); gg = lo + hi;
        unpack2(acc3, lo, hi); go = lo + hi;

        float ia = sigmoid_f(gi);
        float fa = sigmoid_f(gf);
        float ga = tanh_f(gg);
        float oa = sigmoid_f(go);

        c  = fmaf(fa, c, ia * ga);
        hn = oa * tanh_f(c);

        out[(size_t)t * out_stride_t + (size_t)b * HSZ + j] = hn;
        hs[cur ^ 1][bl][j] = hn;
        __syncthreads();
    }

    // final (h, c) appended after outputs if the output buffer includes them
    const long long base = (long long)T_STEPS * BATCH * HSZ;
    if (out_size >= base + 2LL * BATCH * HSZ) {
        out[base + (size_t)b * HSZ + j] = hn;
        out[base + (size_t)BATCH * HSZ + (size_t)b * HSZ + j] = c;
    }
}

extern "C" void kernel_launch(void* const* d_in, const int* in_sizes, int n_in,
                              void* d_out, int out_size) {
    const float* x   = (const float*)d_in[0];  // input_sequence [T,B,I]
    const float* h0  = (const float*)d_in[1];  // initial_h [B,H]
    const float* c0  = (const float*)d_in[2];  // initial_c [B,H]
    const float* Wih = (const float*)d_in[3];  // [4H, I]
    const float* Whh = (const float*)d_in[4];  // [4H, H]
    const float* bih = (const float*)d_in[5];  // [4H]
    const float* bhh = (const float*)d_in[6];  // [4H]
    float* out = (float*)d_out;

    dim3 grid(BATCH / NB);      // 256 blocks
    dim3 block(NTHREADS);       // 320 threads
    lstm_persist_kernel<<<grid, block>>>(x, h0, c0, Wih, Whh, bih, bhh,
                                         out, (long long)out_size);
}

// round 2
// speedup vs baseline: 1.0684x; 1.0684x over previous
#include <cuda_runtime.h>

// LSTM T=512, B=4096, I=10, H=20. Gate-split: 2 threads per (batch,hidden) pair.
//   half0: gates i,f ; owns c recurrence
//   half1: gates g,o ; owns h write (smem + gmem)
// Weights register-resident as f32x2; fma.rn.f32x2 packed math; tanh.approx MUFU;
// x[t+1] software-pipelined. 2 CTAs/SM via __launch_bounds__(320,2).

#define T_STEPS 512
#define BATCH   4096
#define ISZ     10
#define HSZ     20
#define NB      8
#define NTHREADS (NB * HSZ * 2)   // 320

typedef unsigned long long u64;

__device__ __forceinline__ u64 pack2(float x, float y) {
    u64 r;
    asm("mov.b64 %0, {%1,%2};" : "=l"(r) : "f"(x), "f"(y));
    return r;
}
__device__ __forceinline__ void unpack2(u64 v, float& x, float& y) {
    asm("mov.b64 {%0,%1}, %2;" : "=f"(x), "=f"(y) : "l"(v));
}
__device__ __forceinline__ u64 ffma2(u64 a, u64 b, u64 c) {
    u64 r;
    asm("fma.rn.f32x2 %0, %1, %2, %3;" : "=l"(r) : "l"(a), "l"(b), "l"(c));
    return r;
}
__device__ __forceinline__ float tanh_fast(float x) {
    float y;
    asm("tanh.approx.f32 %0, %1;" : "=f"(y) : "f"(x));
    return y;
}
__device__ __forceinline__ float sigmoid_fast(float x) {
    return fmaf(tanh_fast(0.5f * x), 0.5f, 0.5f);   // 1 MUFU + mul + fma
}

__global__ void __launch_bounds__(NTHREADS, 2) lstm_gs_kernel(
    const float* __restrict__ x,      // [T, B, I]
    const float* __restrict__ h0,     // [B, H]
    const float* __restrict__ c0,     // [B, H]
    const float* __restrict__ Wih,    // [4H, I]
    const float* __restrict__ Whh,    // [4H, H]
    const float* __restrict__ bih,    // [4H]
    const float* __restrict__ bhh,    // [4H]
    float* __restrict__ out,
    long long out_size)
{
    const int tid  = threadIdx.x;
    const int pair = tid >> 1;
    const int half = tid & 1;             // 0: gates i,f | 1: gates g,o
    const int bl   = pair / HSZ;          // local row 0..NB-1
    const int j    = pair % HSZ;          // hidden unit
    const int b    = blockIdx.x * NB + bl;

    const int g0 = half ? 2 : 0;          // i or g
    const int g1 = half ? 3 : 1;          // f or o

    // ---- register-resident weights for my two gates ----
    u64 wih2[2][ISZ / 2];
    u64 whh2[2][HSZ / 2];
    u64 acc_init[2];
    {
        const int rows[2] = {g0 * HSZ + j, g1 * HSZ + j};
#pragma unroll
        for (int g = 0; g < 2; g++) {
            const float* wr = Wih + rows[g] * ISZ;
#pragma unroll
            for (int k = 0; k < ISZ / 2; k++)
                wih2[g][k] = *reinterpret_cast<const u64*>(wr + 2 * k);
            const float* wr2 = Whh + rows[g] * HSZ;
#pragma unroll
            for (int k = 0; k < HSZ / 2; k++)
                whh2[g][k] = *reinterpret_cast<const u64*>(wr2 + 2 * k);
            acc_init[g] = pack2(bih[rows[g]] + bhh[rows[g]], 0.0f);
        }
    }

    __shared__ __align__(16) float hs[2][NB][HSZ];   // 1.25 KB

    float c = c0[(size_t)b * HSZ + j];               // live in half0 only
    if (half) hs[0][bl][j] = h0[(size_t)b * HSZ + j];
    __syncthreads();

    const float* xb = x + (size_t)b * ISZ;
    const size_t out_stride_t = (size_t)BATCH * HSZ;

    // prefetch x[0]
    u64 xc[ISZ / 2];
    {
        const float* xp = xb;
#pragma unroll
        for (int k = 0; k < ISZ / 2; k++)
            xc[k] = *reinterpret_cast<const u64*>(xp + 2 * k);
    }

    float hn = 0.0f;   // half1's running h output

    for (int t = 0; t < T_STEPS; t++) {
        const int cur = t & 1;

        // issue x[t+1] loads early (hide DRAM latency under this step)
        u64 xn[ISZ / 2];
        {
            const int tn = (t + 1 < T_STEPS) ? t + 1 : t;
            const float* xp = xb + (size_t)tn * BATCH * ISZ;
#pragma unroll
            for (int k = 0; k < ISZ / 2; k++)
                xn[k] = *reinterpret_cast<const u64*>(xp + 2 * k);
        }

        u64 acc0 = acc_init[0], acc1 = acc_init[1];

        // input projection (x in regs)
#pragma unroll
        for (int k = 0; k < ISZ / 2; k++) {
            acc0 = ffma2(wih2[0][k], xc[k], acc0);
            acc1 = ffma2(wih2[1][k], xc[k], acc1);
        }

        // recurrent projection: h via LDS.128 (2 packed pairs per load)
        const float* hrow = &hs[cur][bl][0];
#pragma unroll
        for (int k = 0; k < HSZ / 4; k++) {
            ulonglong2 h4 = *reinterpret_cast<const ulonglong2*>(hrow + 4 * k);
            acc0 = ffma2(whh2[0][2 * k],     h4.x, acc0);
            acc1 = ffma2(whh2[1][2 * k],     h4.x, acc1);
            acc0 = ffma2(whh2[0][2 * k + 1], h4.y, acc0);
            acc1 = ffma2(whh2[1][2 * k + 1], h4.y, acc1);
        }

        float lo, hi;
        unpack2(acc0, lo, hi);
        const float s0 = lo + hi;    // half0: gate i | half1: gate g
        unpack2(acc1, lo, hi);
        const float s1 = lo + hi;    // half0: gate f | half1: gate o

        // activations: half0 -> sig(i), sig(f); half1 -> tanh(g), sig(o)
        const float a0 = half ? tanh_fast(s0)    : sigmoid_fast(s0);
        const float a1 = sigmoid_fast(s1);

        // half1 -> half0: ga
        const float ga = __shfl_xor_sync(0xFFFFFFFFu, a0, 1);

        float tc = 0.0f;
        if (!half) {                              // c-update on half0
            c  = fmaf(a1, c, a0 * ga);
            tc = tanh_fast(c);
        }
        // half0 -> half1: tanh(c)
        tc = __shfl_xor_sync(0xFFFFFFFFu, tc, 1);

        if (half) {                               // h output on half1
            hn = a1 * tc;
            out[(size_t)t * out_stride_t + (size_t)b * HSZ + j] = hn;
            hs[cur ^ 1][bl][j] = hn;
        }

#pragma unroll
        for (int k = 0; k < ISZ / 2; k++) xc[k] = xn[k];

        __syncthreads();
    }

    // final (h, c) appended after outputs
    const long long base = (long long)T_STEPS * BATCH * HSZ;
    if (out_size >= base + 2LL * BATCH * HSZ) {
        if (half)
            out[base + (size_t)b * HSZ + j] = hn;
        else
            out[base + (size_t)BATCH * HSZ + (size_t)b * HSZ + j] = c;
    }
}

extern "C" void kernel_launch(void* const* d_in, const int* in_sizes, int n_in,
                              void* d_out, int out_size) {
    const float* x   = (const float*)d_in[0];
    const float* h0  = (const float*)d_in[1];
    const float* c0  = (const float*)d_in[2];
    const float* Wih = (const float*)d_in[3];
    const float* Whh = (const float*)d_in[4];
    const float* bih = (const float*)d_in[5];
    const float* bhh = (const float*)d_in[6];
    float* out = (float*)d_out;

    dim3 grid(BATCH / NB);     // 512 CTAs
    dim3 block(NTHREADS);      // 320 threads
    lstm_gs_kernel<<<grid, block>>>(x, h0, c0, Wih, Whh, bih, bhh,
                                    out, (long long)out_size);
}